// round 16
// baseline (speedup 1.0000x reference)
#include <cuda_runtime.h>
#include <cuda_fp16.h>
#include <stdint.h>
#include <math.h>

#define HW 16384
#define RLEN 9088         // padded row: 448 + 128*64 + 448 elems (7-px pads)
#define NROWS 144         // h = -8 .. 135
typedef unsigned u32; typedef unsigned long long u64;

// ---------------- device scratch (zero-initialized; pads never written) ----
__device__ __align__(256) __half g_xA_h[12 * NROWS * RLEN];
__device__ __align__(256) __half g_cA_h[16 * NROWS * RLEN];
__device__ __align__(256) __half g_wb_h[4 * 27 * 4096];
__device__ __align__(256) __half g_wo_h[36 * 4096];

// ---------------- PTX helpers ----------------------------------------------
__device__ __forceinline__ u32 s2u(const void* p){
    u32 a; asm("{ .reg .u64 t; cvta.to.shared.u64 t, %1; cvt.u32.u64 %0, t; }"
               : "=r"(a) : "l"(p)); return a;
}
#define CP16(dst, src) \
    asm volatile("cp.async.cg.shared.global [%0], [%1], 16;" :: "r"(dst), "l"(src) : "memory")
#define CP_COMMIT() asm volatile("cp.async.commit_group;" ::: "memory")
#define CP_WAIT1()  asm volatile("cp.async.wait_group 1;" ::: "memory")
#define LDX4(r, a) \
    asm volatile("ldmatrix.sync.aligned.m8n8.x4.shared.b16 {%0,%1,%2,%3}, [%4];" \
        : "=r"((r)[0]), "=r"((r)[1]), "=r"((r)[2]), "=r"((r)[3]) : "r"(a))
#define MMA(d, a, b0, b1) \
    asm("mma.sync.aligned.m16n8k16.row.col.f32.f16.f16.f32 " \
        "{%0,%1,%2,%3},{%4,%5,%6,%7},{%8,%9},{%0,%1,%2,%3};" \
        : "+f"((d)[0]), "+f"((d)[1]), "+f"((d)[2]), "+f"((d)[3]) \
        : "r"((a)[0]), "r"((a)[1]), "r"((a)[2]), "r"((a)[3]), "r"(b0), "r"(b1))

__device__ __forceinline__ u32 pack2h(float v0, float v1){
    __half h0 = __float2half_rn(v0);
    __half h1 = __float2half_rn(v1);
    return (u32)*(unsigned short*)&h0 | ((u32)*(unsigned short*)&h1 << 16);
}

// ---------------- fused: mask conv + softmax + xm transpose ------------------
// One block per (b, h). x rows h-1..h+1 x 64ch staged once in smem.
#define SXS 133     // padded w stride (conflict-free: 399 words % 32 = 15)
__global__ void __launch_bounds__(256)
mask_xm_kernel(const float* __restrict__ x, const float* __restrict__ mw,
               const float* __restrict__ mb, float* __restrict__ masks)
{
    extern __shared__ float sx[];           // [c][r][w] : 64*3*133 floats
    __shared__ float s_mw[1728];
    __shared__ float ps[384];               // partial sums (upper half)
    __shared__ float smk[384];              // final masks
    int bx = blockIdx.x;                    // (b<<7)|h
    int h = bx & 127, b = bx >> 7;
    int tid = threadIdx.x;

    for (int i = tid; i < 1728; i += 256) s_mw[i] = mw[i];
    for (int idx = tid; idx < 64*3*128; idx += 256){
        int w = idx & 127, r = (idx >> 7) % 3, c = idx / 384;
        int hh = h + r - 1;
        float v = 0.f;
        if ((unsigned)hh < 128u) v = x[((size_t)(b*64 + c))*HW + hh*128 + w];
        sx[(c*3 + r)*SXS + w] = v;
    }
    __syncthreads();

    // mask conv: lower half threads do ch 0-31, upper half ch 32-63
    {
        int w = tid & 127;
        int cbeg = (tid >> 7) * 32;
        float a0 = 0.f, a1 = 0.f, a2 = 0.f;
        for (int c = cbeg; c < cbeg + 32; c++){
            const float* wc = s_mw + c*9;
            #pragma unroll
            for (int kh = 0; kh < 3; kh++){
                const float* row = sx + (c*3 + kh)*SXS;
                #pragma unroll
                for (int kw = 0; kw < 3; kw++){
                    int ww = w + kw - 1;
                    if ((unsigned)ww >= 128u) continue;
                    float v = row[ww]; int t = kh*3 + kw;
                    a0 = fmaf(v, wc[t], a0);
                    a1 = fmaf(v, wc[576 + t], a1);
                    a2 = fmaf(v, wc[1152 + t], a2);
                }
            }
        }
        if (tid >= 128){ ps[w] = a0; ps[128 + w] = a1; ps[256 + w] = a2; }
        __syncthreads();
        if (tid < 128){
            a0 += ps[w] + mb[0]; a1 += ps[128 + w] + mb[1]; a2 += ps[256 + w] + mb[2];
            float mx = fmaxf(a0, fmaxf(a1, a2));
            float e0 = expf(a0 - mx), e1 = expf(a1 - mx), e2 = expf(a2 - mx);
            float inv = 1.f/(e0 + e1 + e2);
            e0 *= inv; e1 *= inv; e2 *= inv;
            masks[((size_t)(b*3 + 0))*HW + h*128 + w] = e0;
            masks[((size_t)(b*3 + 1))*HW + h*128 + w] = e1;
            masks[((size_t)(b*3 + 2))*HW + h*128 + w] = e2;
            smk[w] = e0; smk[128 + w] = e1; smk[256 + w] = e2;
        }
        __syncthreads();
    }

    // xm transpose: [m][w][c] fp16 into padded layout
    for (int idx = tid; idx < 3*128*32; idx += 256){
        int c2 = (idx & 31)*2, w = (idx >> 5) & 127, m = idx >> 12;
        float s = smk[m*128 + w];
        float v0 = sx[(c2*3 + 1)*SXS + w] * s;
        float v1 = sx[((c2 + 1)*3 + 1)*SXS + w] * s;
        size_t e = ((size_t)(b*3 + m)*NROWS + h + 8)*RLEN + 448 + (size_t)w*64 + c2;
        *(u32*)(g_xA_h + e) = pack2h(v0, v1);
    }
}

// ---------------- weight prep (coalesced via smem staging) -------------------
// branch: block per (b, m). reads kern[b,m,:,:,:] contiguous, writes 9 tap tiles.
__global__ void __launch_bounds__(256)
wprep_b_kernel(const float* __restrict__ kern)
{
    __shared__ __half sw[36864];            // [o][c][tap]
    int bm = blockIdx.x;                    // b*3 + m
    int b = bm / 3, m = bm - b*3;
    const float* src = kern + (size_t)bm * 36864;
    for (int i = threadIdx.x; i < 36864; i += 256)
        sw[i] = __float2half_rn(src[i]);
    __syncthreads();
    // write: tile = b*27 + tap*3 + m, element o*64 + c  <- sw[o*576 + c*9 + tap]
    for (int i = threadIdx.x; i < 9*4096; i += 256){
        int tap = i >> 12, e = i & 4095, o = e >> 6, c = e & 63;
        g_wb_h[((size_t)(b*27) + tap*3 + m)*4096 + e] = sw[o*576 + c*9 + tap];
    }
}

// out: block per 8-o chunk. reads cow[o0..o0+8) contiguous.
__global__ void __launch_bounds__(256)
wprep_o_kernel(const float* __restrict__ cow)
{
    __shared__ __half sw[8*2304];           // [o8][ic][tap]
    int o0 = blockIdx.x * 8;
    const float* src = cow + (size_t)o0 * 2304;
    for (int i = threadIdx.x; i < 8*2304; i += 256)
        sw[i] = __float2half_rn(src[i]);
    __syncthreads();
    // write: tile = tap*4 + ch, element (o0+o8)*64 + c  <- sw[o8*2304 + (ch*64+c)*9 + tap]
    for (int i = threadIdx.x; i < 9*4*8*64; i += 256){
        int c   = i & 63;
        int o8  = (i >> 6) & 7;
        int ch  = (i >> 9) & 3;
        int tap = i >> 11;
        g_wo_h[((size_t)(tap*4 + ch))*4096 + (o0 + o8)*64 + c]
            = sw[o8*2304 + (ch*64 + c)*9 + tap];
    }
}

// ---------------- MMA mainloop: M=256 (2 output rows), 256 thr, dbl-buffer --
// Stage: A 256x72 fp16 (36864B) + B 64x72 (9216B) = 46080B; 2 stages -> 2 CTA/SM.
template<int NS, int NCH>
__device__ __forceinline__ void mma_mainloop(
    const __half* __restrict__ xah, const __half* __restrict__ wth,
    int d, int h0, float acc0[8][4], float acc1[8][4])
{
    constexpr u32 B_OFF = 36864u;
    constexpr u32 BUFSZ = 46080u;

    extern __shared__ __align__(16) unsigned char smraw[];
    u32 sm0 = s2u(smraw);
    const int tid = threadIdx.x, lane = tid & 31, wid = tid >> 5;

    #pragma unroll
    for (int i = 0; i < 8; i++)
        #pragma unroll
        for (int j = 0; j < 4; j++){ acc0[i][j] = 0.f; acc1[i][j] = 0.f; }

    auto issue = [&](int s, int buf){
        int tap = s / NCH, ch = s - tap*NCH;
        int dh = (tap/3 - 1)*d, dw = (tap%3 - 1)*d;
        size_t arow = ((size_t)ch*NROWS + (h0 + 8 + dh))*RLEN + 448 + (long)dw*64;
        u32 abase = sm0 + (u32)buf*BUFSZ;
        #pragma unroll
        for (int t = 0; t < 8; t++){
            int idx = tid + t*256;
            int r = idx >> 3, c16 = idx & 7;
            size_t off = arow + (size_t)(r >> 7)*RLEN + (size_t)(r & 127)*64 + c16*8;
            CP16(abase + (u32)(r*144 + c16*16), xah + off);
        }
        u32 bbase = abase + B_OFF;
        const __half* wsh = wth + (size_t)s*4096;
        #pragma unroll
        for (int t = 0; t < 2; t++){
            int idx = tid + t*256; int o = idx >> 3, c16 = idx & 7;
            CP16(bbase + (u32)(o*144 + c16*16), wsh + o*64 + c16*8);
        }
    };

    issue(0, 0); CP_COMMIT();
    issue(1, 1); CP_COMMIT();

    const u32 a_lane = (u32)((wid*16 + (lane & 15))*144 + (lane >> 4)*16);
    const int br = lane & 7, bq = lane >> 3;
    const u32 b_lane0 = (u32)((br + (bq >> 1)*8)*144 + (bq & 1)*16);

    for (int s = 0; s < NS; s++){
        int buf = s & 1;
        CP_WAIT1();
        __syncthreads();
        u32 ab0 = sm0 + (u32)buf*BUFSZ + a_lane;
        u32 ab1 = ab0 + 128u*144u;
        u32 bb  = sm0 + (u32)buf*BUFSZ + B_OFF + b_lane0;
        #pragma unroll
        for (int ks = 0; ks < 4; ks++){
            u32 ah0[4], ah1[4];
            LDX4(ah0, ab0 + ks*32);
            LDX4(ah1, ab1 + ks*32);
            #pragma unroll
            for (int np = 0; np < 4; np++){
                u32 bh[4];
                LDX4(bh, bb + (u32)(np*16*144) + ks*32);
                MMA(acc0[2*np],   ah0, bh[0], bh[1]);
                MMA(acc0[2*np+1], ah0, bh[2], bh[3]);
                MMA(acc1[2*np],   ah1, bh[0], bh[1]);
                MMA(acc1[2*np+1], ah1, bh[2], bh[3]);
            }
        }
        __syncthreads();
        if (s + 2 < NS) issue(s + 2, buf);
        CP_COMMIT();
    }
}

// ---------------- branch conv: writes fp16 cat tiles -------------------------
__global__ void __launch_bounds__(256, 2)
branch_mma()
{
    int bx = blockIdx.x;                  // hp | di<<6 | b<<8
    int hp = bx & 63, di = (bx >> 6) & 3, b = bx >> 8;
    int d = 2*di + 1, h0 = hp*2;

    float acc0[8][4], acc1[8][4];
    mma_mainloop<27, 3>(g_xA_h + (size_t)(b*3)*NROWS*RLEN,
                        g_wb_h + (size_t)b*27*4096, d, h0, acc0, acc1);

    const int lane = threadIdx.x & 31, wid = threadIdx.x >> 5;
    const int w0 = wid*16, g = lane >> 2, tig = lane & 3;
    size_t cb0 = ((size_t)(b*4 + di)*NROWS + (h0 + 8))*RLEN + 448;
    size_t cb1 = cb0 + RLEN;
    #pragma unroll
    for (int nt = 0; nt < 8; nt++){
        int o = nt*8 + 2*tig;
        *(u32*)(g_cA_h + cb0 + (size_t)(w0 + g)*64 + o)     = pack2h(acc0[nt][0], acc0[nt][1]);
        *(u32*)(g_cA_h + cb0 + (size_t)(w0 + g + 8)*64 + o) = pack2h(acc0[nt][2], acc0[nt][3]);
        *(u32*)(g_cA_h + cb1 + (size_t)(w0 + g)*64 + o)     = pack2h(acc1[nt][0], acc1[nt][1]);
        *(u32*)(g_cA_h + cb1 + (size_t)(w0 + g + 8)*64 + o) = pack2h(acc1[nt][2], acc1[nt][3]);
    }
}

// ---------------- out conv + bias + BN + ReLU --------------------------------
__global__ void __launch_bounds__(256, 2)
out_mma(const float* __restrict__ cob, const float* __restrict__ gamma,
        const float* __restrict__ beta, const float* __restrict__ mean,
        const float* __restrict__ var, float* __restrict__ out)
{
    __shared__ float sInv[64], sAdd[64], sBias[64];
    int bx = blockIdx.x;                  // hp | b<<6
    int hp = bx & 63, b = bx >> 6;
    int h0 = hp*2;
    if (threadIdx.x < 64){
        int o = threadIdx.x;
        float inv = gamma[o] * rsqrtf(var[o] + 1e-5f);
        sInv[o] = inv; sAdd[o] = beta[o] - mean[o]*inv; sBias[o] = cob[o];
    }

    float acc0[8][4], acc1[8][4];
    mma_mainloop<36, 4>(g_cA_h + (size_t)(b*4)*NROWS*RLEN, g_wo_h, 1, h0, acc0, acc1);

    const int lane = threadIdx.x & 31, wid = threadIdx.x >> 5;
    const int w0 = wid*16, g = lane >> 2, tig = lane & 3;
    #pragma unroll
    for (int nt = 0; nt < 8; nt++){
        int o = nt*8 + 2*tig;
        float i0 = sInv[o], a0 = sAdd[o], c0 = sBias[o];
        float i1 = sInv[o+1], a1 = sAdd[o+1], c1 = sBias[o+1];
        float* p0 = out + ((size_t)(b*64 + o))*HW + h0*128;
        float* p1 = p0 + HW;
        p0[w0 + g]           = fmaxf((acc0[nt][0] + c0)*i0 + a0, 0.f);
        p1[w0 + g]           = fmaxf((acc0[nt][1] + c1)*i1 + a1, 0.f);
        p0[w0 + g + 8]       = fmaxf((acc0[nt][2] + c0)*i0 + a0, 0.f);
        p1[w0 + g + 8]       = fmaxf((acc0[nt][3] + c1)*i1 + a1, 0.f);
        p0[128 + w0 + g]     = fmaxf((acc1[nt][0] + c0)*i0 + a0, 0.f);
        p1[128 + w0 + g]     = fmaxf((acc1[nt][1] + c1)*i1 + a1, 0.f);
        p0[128 + w0 + g + 8] = fmaxf((acc1[nt][2] + c0)*i0 + a0, 0.f);
        p1[128 + w0 + g + 8] = fmaxf((acc1[nt][3] + c1)*i1 + a1, 0.f);
    }
}

// ---------------- host --------------------------------------------------------
extern "C" void kernel_launch(void* const* d_in, const int* in_sizes, int n_in,
                              void* d_out, int out_size)
{
    const float* x     = (const float*)d_in[0];
    const float* kern  = (const float*)d_in[1];
    const float* mw    = (const float*)d_in[2];
    const float* mb    = (const float*)d_in[3];
    const float* cow   = (const float*)d_in[4];
    const float* cob   = (const float*)d_in[5];
    const float* gamma = (const float*)d_in[6];
    const float* beta  = (const float*)d_in[7];
    const float* mean  = (const float*)d_in[8];
    const float* var   = (const float*)d_in[9];
    float* out   = (float*)d_out;
    float* masks = out + 4*64*HW;

    const int SMEM    = 2 * 46080;             // 92160 -> 2 CTAs/SM
    const int SMEM_MX = 64*3*SXS*4;            // 102144
    cudaFuncSetAttribute(branch_mma,     cudaFuncAttributeMaxDynamicSharedMemorySize, SMEM);
    cudaFuncSetAttribute(out_mma,        cudaFuncAttributeMaxDynamicSharedMemorySize, SMEM);
    cudaFuncSetAttribute(mask_xm_kernel, cudaFuncAttributeMaxDynamicSharedMemorySize, SMEM_MX);

    mask_xm_kernel<<<512, 256, SMEM_MX>>>(x, mw, mb, masks);
    wprep_b_kernel<<<12, 256>>>(kern);
    wprep_o_kernel<<<8, 256>>>(cow);
    branch_mma<<<1024, 256, SMEM>>>();
    out_mma<<<256, 256, SMEM>>>(cob, gamma, beta, mean, var, out);
}

// round 17
// speedup vs baseline: 1.0418x; 1.0418x over previous
#include <cuda_runtime.h>
#include <cuda_fp16.h>
#include <stdint.h>
#include <math.h>

#define HW 16384
#define RLEN 9088         // padded row: 448 + 128*64 + 448 elems (7-px pads)
#define NROWS 144         // h = -8 .. 135
typedef unsigned u32; typedef unsigned long long u64;

// ---------------- device scratch (zero-initialized; pads never written) ----
__device__ __align__(256) __half g_xA_h[12 * NROWS * RLEN];
__device__ __align__(256) __half g_cA_h[16 * NROWS * RLEN];
__device__ __align__(256) __half g_wb_h[4 * 27 * 4096];
__device__ __align__(256) __half g_wo_h[36 * 4096];

// ---------------- PTX helpers ----------------------------------------------
__device__ __forceinline__ u32 s2u(const void* p){
    u32 a; asm("{ .reg .u64 t; cvta.to.shared.u64 t, %1; cvt.u32.u64 %0, t; }"
               : "=r"(a) : "l"(p)); return a;
}
#define CP16(dst, src) \
    asm volatile("cp.async.cg.shared.global [%0], [%1], 16;" :: "r"(dst), "l"(src) : "memory")
#define CP_COMMIT() asm volatile("cp.async.commit_group;" ::: "memory")
#define CP_WAIT1()  asm volatile("cp.async.wait_group 1;" ::: "memory")
#define LDX4(r, a) \
    asm volatile("ldmatrix.sync.aligned.m8n8.x4.shared.b16 {%0,%1,%2,%3}, [%4];" \
        : "=r"((r)[0]), "=r"((r)[1]), "=r"((r)[2]), "=r"((r)[3]) : "r"(a))
#define MMA(d, a, b0, b1) \
    asm("mma.sync.aligned.m16n8k16.row.col.f32.f16.f16.f32 " \
        "{%0,%1,%2,%3},{%4,%5,%6,%7},{%8,%9},{%0,%1,%2,%3};" \
        : "+f"((d)[0]), "+f"((d)[1]), "+f"((d)[2]), "+f"((d)[3]) \
        : "r"((a)[0]), "r"((a)[1]), "r"((a)[2]), "r"((a)[3]), "r"(b0), "r"(b1))

__device__ __forceinline__ u32 pack2h(float v0, float v1){
    __half h0 = __float2half_rn(v0);
    __half h1 = __float2half_rn(v1);
    return (u32)*(unsigned short*)&h0 | ((u32)*(unsigned short*)&h1 << 16);
}

// ---------------- stage 1: mask conv + softmax (R15 version) ----------------
__global__ void mask_kernel(const float* __restrict__ x, const float* __restrict__ mw,
                            const float* __restrict__ mb, float* __restrict__ masks)
{
    __shared__ float s_mw[3*64*9];
    for (int i = threadIdx.x; i < 3*64*9; i += 256) s_mw[i] = mw[i];
    __syncthreads();
    int gid = blockIdx.x*256 + threadIdx.x;
    int b = gid >> 14, pid = gid & (HW-1), h = pid >> 7, w = pid & 127;
    float a0 = mb[0], a1 = mb[1], a2 = mb[2];
    const float* xb = x + b*64*HW;
    for (int c = 0; c < 64; c++){
        const float* xc = xb + c*HW; const float* wc = s_mw + c*9;
        #pragma unroll
        for (int kh = 0; kh < 3; kh++){
            int hh = h + kh - 1; if ((unsigned)hh >= 128u) continue;
            #pragma unroll
            for (int kw = 0; kw < 3; kw++){
                int ww = w + kw - 1; if ((unsigned)ww >= 128u) continue;
                float v = xc[hh*128 + ww]; int t = kh*3 + kw;
                a0 = fmaf(v, wc[t], a0); a1 = fmaf(v, wc[576+t], a1); a2 = fmaf(v, wc[1152+t], a2);
            }
        }
    }
    float mx = fmaxf(a0, fmaxf(a1, a2));
    float e0 = expf(a0-mx), e1 = expf(a1-mx), e2 = expf(a2-mx);
    float inv = 1.f/(e0+e1+e2);
    masks[(b*3+0)*HW+pid] = e0*inv; masks[(b*3+1)*HW+pid] = e1*inv; masks[(b*3+2)*HW+pid] = e2*inv;
}

// ---------------- stage 2: xm transpose, x row read ONCE for all 3 masks ----
__global__ void __launch_bounds__(256)
xmT_kernel(const float* __restrict__ x, const float* __restrict__ masks)
{
    __shared__ float sx[64*129];
    __shared__ float smk[384];
    int bx = blockIdx.x;                 // (b<<7)|h
    int h = bx & 127, b = bx >> 7;
    int tid = threadIdx.x;
    for (int idx = tid; idx < 8192; idx += 256){
        int c = idx >> 7, w = idx & 127;
        sx[c*129 + w] = x[((size_t)(b*64 + c))*HW + h*128 + w];
    }
    for (int idx = tid; idx < 384; idx += 256){
        int m = idx >> 7, w = idx & 127;
        smk[idx] = masks[((size_t)(b*3 + m))*HW + h*128 + w];
    }
    __syncthreads();
    for (int idx = tid; idx < 3*128*32; idx += 256){
        int c2 = (idx & 31)*2, w = (idx >> 5) & 127, m = idx >> 12;
        float s = smk[m*128 + w];
        float v0 = sx[c2*129 + w] * s;
        float v1 = sx[(c2 + 1)*129 + w] * s;
        size_t e = ((size_t)(b*3 + m)*NROWS + h + 8)*RLEN + 448 + (size_t)w*64 + c2;
        *(u32*)(g_xA_h + e) = pack2h(v0, v1);
    }
}

// ---------------- weight prep (coalesced via smem staging) -------------------
__global__ void __launch_bounds__(256)
wprep_b_kernel(const float* __restrict__ kern)
{
    __shared__ __half sw[36864];            // [o][c][tap]
    int bm = blockIdx.x;                    // b*3 + m
    int b = bm / 3, m = bm - b*3;
    const float* src = kern + (size_t)bm * 36864;
    for (int i = threadIdx.x; i < 36864; i += 256)
        sw[i] = __float2half_rn(src[i]);
    __syncthreads();
    for (int i = threadIdx.x; i < 9*4096; i += 256){
        int tap = i >> 12, e = i & 4095, o = e >> 6, c = e & 63;
        g_wb_h[((size_t)(b*27) + tap*3 + m)*4096 + e] = sw[o*576 + c*9 + tap];
    }
}

__global__ void __launch_bounds__(256)
wprep_o_kernel(const float* __restrict__ cow)
{
    __shared__ __half sw[8*2304];           // [o8][ic][tap]
    int o0 = blockIdx.x * 8;
    const float* src = cow + (size_t)o0 * 2304;
    for (int i = threadIdx.x; i < 8*2304; i += 256)
        sw[i] = __float2half_rn(src[i]);
    __syncthreads();
    for (int i = threadIdx.x; i < 9*4*8*64; i += 256){
        int c   = i & 63;
        int o8  = (i >> 6) & 7;
        int ch  = (i >> 9) & 3;
        int tap = i >> 11;
        g_wo_h[((size_t)(tap*4 + ch))*4096 + (o0 + o8)*64 + c]
            = sw[o8*2304 + (ch*64 + c)*9 + tap];
    }
}

// ---------------- MMA mainloop: M=256 (2 output rows), 256 thr, dbl-buffer --
// Stage: A 256x72 fp16 (36864B) + B 64x72 (9216B) = 46080B; 2 stages -> 2 CTA/SM.
template<int NS, int NCH>
__device__ __forceinline__ void mma_mainloop(
    const __half* __restrict__ xah, const __half* __restrict__ wth,
    int d, int h0, float acc0[8][4], float acc1[8][4])
{
    constexpr u32 B_OFF = 36864u;
    constexpr u32 BUFSZ = 46080u;

    extern __shared__ __align__(16) unsigned char smraw[];
    u32 sm0 = s2u(smraw);
    const int tid = threadIdx.x, lane = tid & 31, wid = tid >> 5;

    #pragma unroll
    for (int i = 0; i < 8; i++)
        #pragma unroll
        for (int j = 0; j < 4; j++){ acc0[i][j] = 0.f; acc1[i][j] = 0.f; }

    auto issue = [&](int s, int buf){
        int tap = s / NCH, ch = s - tap*NCH;
        int dh = (tap/3 - 1)*d, dw = (tap%3 - 1)*d;
        size_t arow = ((size_t)ch*NROWS + (h0 + 8 + dh))*RLEN + 448 + (long)dw*64;
        u32 abase = sm0 + (u32)buf*BUFSZ;
        #pragma unroll
        for (int t = 0; t < 8; t++){
            int idx = tid + t*256;
            int r = idx >> 3, c16 = idx & 7;
            size_t off = arow + (size_t)(r >> 7)*RLEN + (size_t)(r & 127)*64 + c16*8;
            CP16(abase + (u32)(r*144 + c16*16), xah + off);
        }
        u32 bbase = abase + B_OFF;
        const __half* wsh = wth + (size_t)s*4096;
        #pragma unroll
        for (int t = 0; t < 2; t++){
            int idx = tid + t*256; int o = idx >> 3, c16 = idx & 7;
            CP16(bbase + (u32)(o*144 + c16*16), wsh + o*64 + c16*8);
        }
    };

    issue(0, 0); CP_COMMIT();
    issue(1, 1); CP_COMMIT();

    const u32 a_lane = (u32)((wid*16 + (lane & 15))*144 + (lane >> 4)*16);
    const int br = lane & 7, bq = lane >> 3;
    const u32 b_lane0 = (u32)((br + (bq >> 1)*8)*144 + (bq & 1)*16);

    for (int s = 0; s < NS; s++){
        int buf = s & 1;
        CP_WAIT1();
        __syncthreads();
        u32 ab0 = sm0 + (u32)buf*BUFSZ + a_lane;
        u32 ab1 = ab0 + 128u*144u;
        u32 bb  = sm0 + (u32)buf*BUFSZ + B_OFF + b_lane0;
        #pragma unroll
        for (int ks = 0; ks < 4; ks++){
            u32 ah0[4], ah1[4];
            LDX4(ah0, ab0 + ks*32);
            LDX4(ah1, ab1 + ks*32);
            #pragma unroll
            for (int np = 0; np < 4; np++){
                u32 bh[4];
                LDX4(bh, bb + (u32)(np*16*144) + ks*32);
                MMA(acc0[2*np],   ah0, bh[0], bh[1]);
                MMA(acc0[2*np+1], ah0, bh[2], bh[3]);
                MMA(acc1[2*np],   ah1, bh[0], bh[1]);
                MMA(acc1[2*np+1], ah1, bh[2], bh[3]);
            }
        }
        __syncthreads();
        if (s + 2 < NS) issue(s + 2, buf);
        CP_COMMIT();
    }
}

// ---------------- branch conv: writes fp16 cat tiles -------------------------
__global__ void __launch_bounds__(256, 2)
branch_mma()
{
    int bx = blockIdx.x;                  // hp | di<<6 | b<<8
    int hp = bx & 63, di = (bx >> 6) & 3, b = bx >> 8;
    int d = 2*di + 1, h0 = hp*2;

    float acc0[8][4], acc1[8][4];
    mma_mainloop<27, 3>(g_xA_h + (size_t)(b*3)*NROWS*RLEN,
                        g_wb_h + (size_t)b*27*4096, d, h0, acc0, acc1);

    const int lane = threadIdx.x & 31, wid = threadIdx.x >> 5;
    const int w0 = wid*16, g = lane >> 2, tig = lane & 3;
    size_t cb0 = ((size_t)(b*4 + di)*NROWS + (h0 + 8))*RLEN + 448;
    size_t cb1 = cb0 + RLEN;
    #pragma unroll
    for (int nt = 0; nt < 8; nt++){
        int o = nt*8 + 2*tig;
        *(u32*)(g_cA_h + cb0 + (size_t)(w0 + g)*64 + o)     = pack2h(acc0[nt][0], acc0[nt][1]);
        *(u32*)(g_cA_h + cb0 + (size_t)(w0 + g + 8)*64 + o) = pack2h(acc0[nt][2], acc0[nt][3]);
        *(u32*)(g_cA_h + cb1 + (size_t)(w0 + g)*64 + o)     = pack2h(acc1[nt][0], acc1[nt][1]);
        *(u32*)(g_cA_h + cb1 + (size_t)(w0 + g + 8)*64 + o) = pack2h(acc1[nt][2], acc1[nt][3]);
    }
}

// ---------------- out conv + bias + BN + ReLU --------------------------------
__global__ void __launch_bounds__(256, 2)
out_mma(const float* __restrict__ cob, const float* __restrict__ gamma,
        const float* __restrict__ beta, const float* __restrict__ mean,
        const float* __restrict__ var, float* __restrict__ out)
{
    __shared__ float sInv[64], sAdd[64], sBias[64];
    int bx = blockIdx.x;                  // hp | b<<6
    int hp = bx & 63, b = bx >> 6;
    int h0 = hp*2;
    if (threadIdx.x < 64){
        int o = threadIdx.x;
        float inv = gamma[o] * rsqrtf(var[o] + 1e-5f);
        sInv[o] = inv; sAdd[o] = beta[o] - mean[o]*inv; sBias[o] = cob[o];
    }

    float acc0[8][4], acc1[8][4];
    mma_mainloop<36, 4>(g_cA_h + (size_t)(b*4)*NROWS*RLEN, g_wo_h, 1, h0, acc0, acc1);

    const int lane = threadIdx.x & 31, wid = threadIdx.x >> 5;
    const int w0 = wid*16, g = lane >> 2, tig = lane & 3;
    #pragma unroll
    for (int nt = 0; nt < 8; nt++){
        int o = nt*8 + 2*tig;
        float i0 = sInv[o], a0 = sAdd[o], c0 = sBias[o];
        float i1 = sInv[o+1], a1 = sAdd[o+1], c1 = sBias[o+1];
        float* p0 = out + ((size_t)(b*64 + o))*HW + h0*128;
        float* p1 = p0 + HW;
        p0[w0 + g]           = fmaxf((acc0[nt][0] + c0)*i0 + a0, 0.f);
        p1[w0 + g]           = fmaxf((acc0[nt][1] + c1)*i1 + a1, 0.f);
        p0[w0 + g + 8]       = fmaxf((acc0[nt][2] + c0)*i0 + a0, 0.f);
        p1[w0 + g + 8]       = fmaxf((acc0[nt][3] + c1)*i1 + a1, 0.f);
        p0[128 + w0 + g]     = fmaxf((acc1[nt][0] + c0)*i0 + a0, 0.f);
        p1[128 + w0 + g]     = fmaxf((acc1[nt][1] + c1)*i1 + a1, 0.f);
        p0[128 + w0 + g + 8] = fmaxf((acc1[nt][2] + c0)*i0 + a0, 0.f);
        p1[128 + w0 + g + 8] = fmaxf((acc1[nt][3] + c1)*i1 + a1, 0.f);
    }
}

// ---------------- host --------------------------------------------------------
extern "C" void kernel_launch(void* const* d_in, const int* in_sizes, int n_in,
                              void* d_out, int out_size)
{
    const float* x     = (const float*)d_in[0];
    const float* kern  = (const float*)d_in[1];
    const float* mw    = (const float*)d_in[2];
    const float* mb    = (const float*)d_in[3];
    const float* cow   = (const float*)d_in[4];
    const float* cob   = (const float*)d_in[5];
    const float* gamma = (const float*)d_in[6];
    const float* beta  = (const float*)d_in[7];
    const float* mean  = (const float*)d_in[8];
    const float* var   = (const float*)d_in[9];
    float* out   = (float*)d_out;
    float* masks = out + 4*64*HW;

    const int SMEM = 2 * 46080;             // 92160 -> 2 CTAs/SM
    cudaFuncSetAttribute(branch_mma, cudaFuncAttributeMaxDynamicSharedMemorySize, SMEM);
    cudaFuncSetAttribute(out_mma,    cudaFuncAttributeMaxDynamicSharedMemorySize, SMEM);

    mask_kernel<<<256, 256>>>(x, mw, mb, masks);
    xmT_kernel<<<512, 256>>>(x, masks);
    wprep_b_kernel<<<12, 256>>>(kern);
    wprep_o_kernel<<<8, 256>>>(cow);
    branch_mma<<<1024, 256, SMEM>>>();
    out_mma<<<256, 256, SMEM>>>(cob, gamma, beta, mean, var, out);
}